// round 1
// baseline (speedup 1.0000x reference)
#include <cuda_runtime.h>
#include <cstdint>

// TitansMemory: B=16, L=8192, DK=DV=128.
// Row-decoupled delta-rule recurrence: 2048 independent (b,v) chains.
// 1 warp per chain; 16 warps/CTA share batch b; k/q/v staged in SMEM via
// cp.async double buffering (16-step chunks). State W[v,:], m[v,:] live in
// registers (4 floats/lane each), math in packed f32x2.

#define CSTEPS 16
#define L_SEQ  8192
#define NCH    (L_SEQ / CSTEPS)
#define DK     128
#define DV     128

using ull = unsigned long long;

__device__ __forceinline__ ull pk(float lo, float hi) {
    ull r; asm("mov.b64 %0,{%1,%2};" : "=l"(r) : "f"(lo), "f"(hi)); return r;
}
__device__ __forceinline__ float hadd2(ull p) {
    float lo, hi; asm("mov.b64 {%0,%1},%2;" : "=f"(lo), "=f"(hi) : "l"(p));
    return lo + hi;
}
__device__ __forceinline__ ull mul2(ull a, ull b) {
    ull d; asm("mul.rn.f32x2 %0,%1,%2;" : "=l"(d) : "l"(a), "l"(b)); return d;
}
__device__ __forceinline__ ull fma2(ull a, ull b, ull c) {
    ull d; asm("fma.rn.f32x2 %0,%1,%2,%3;" : "=l"(d) : "l"(a), "l"(b), "l"(c)); return d;
}
__device__ __forceinline__ unsigned su32(const void* p) {
    return (unsigned)__cvta_generic_to_shared(p);
}
__device__ __forceinline__ void cp16(unsigned s, const void* g) {
    asm volatile("cp.async.cg.shared.global [%0],[%1],16;" :: "r"(s), "l"(g));
}
__device__ __forceinline__ void cp4(unsigned s, const void* g) {
    asm volatile("cp.async.ca.shared.global [%0],[%1],4;" :: "r"(s), "l"(g));
}
__device__ __forceinline__ void cp_commit() {
    asm volatile("cp.async.commit_group;" ::: "memory");
}
__device__ __forceinline__ void cp_wait_all() {
    asm volatile("cp.async.wait_group 0;" ::: "memory");
}

__global__ __launch_bounds__(512, 1)
void titans_kernel(const float* __restrict__ Q,
                   const float* __restrict__ K,
                   const float* __restrict__ V,
                   float* __restrict__ Y) {
    __shared__ float k_buf[2][CSTEPS][DK];
    __shared__ float q_buf[2][CSTEPS][DK];
    __shared__ float v_buf[2][CSTEPS][16];
    __shared__ float y_buf[2][CSTEPS][16];

    const int tid   = threadIdx.x;
    const int wid   = tid >> 5;        // 0..15 -> v within group
    const int lane  = tid & 31;
    const int b     = blockIdx.x >> 3;        // 0..15
    const int vbase = (blockIdx.x & 7) << 4;  // 0,16,...,112

    const size_t base = (size_t)b * L_SEQ * DK;
    const float* gk = K + base;
    const float* gq = Q + base;
    const float* gv = V + base;
    float*       gy = Y + base;

    // Constants: c1 = 1-ALPHA = 0.98, beta = 0.9,
    //   U = c1*W - (LR*BETA)*m = 0.98*W - 0.09*m
    //   m' = beta*m + 0.2*r*k     (0.2 = 2*(1-beta))
    //   W' = U - 0.02*r*k         (0.02 = LR*0.2)
    //   y  = U.q - 0.02*r*(k.q)
    const ull C1    = pk(0.98f, 0.98f);
    const ull NLRB  = pk(-0.09f, -0.09f);
    const ull BETA2 = pk(0.9f, 0.9f);

    // chain state in registers: lane owns W[v, 4*lane .. 4*lane+3], same for m
    ull W01 = 0, W23 = 0, m01 = 0, m23 = 0;

    // ---- preload chunk 0 ----
    {
        // k,q: 2048 floats each, 512 threads -> one float4 per thread
        cp16(su32(&k_buf[0][0][0]) + tid * 16, gk + tid * 4);
        cp16(su32(&q_buf[0][0][0]) + tid * 16, gq + tid * 4);
        if (tid < CSTEPS * 16) {
            int i = tid >> 4, j = tid & 15;
            cp4(su32(&v_buf[0][i][j]), gv + (size_t)i * DK + vbase + j);
        }
        cp_commit();
        cp_wait_all();
        __syncthreads();
    }

    for (int chunk = 0; chunk < NCH; ++chunk) {
        const int cur = chunk & 1;
        const int t0  = chunk * CSTEPS;

        // issue loads for next chunk into the other buffer
        if (chunk + 1 < NCH) {
            const int nb  = cur ^ 1;
            const size_t nt = (size_t)(t0 + CSTEPS) * DK;
            cp16(su32(&k_buf[nb][0][0]) + tid * 16, gk + nt + tid * 4);
            cp16(su32(&q_buf[nb][0][0]) + tid * 16, gq + nt + tid * 4);
            if (tid < CSTEPS * 16) {
                int i = tid >> 4, j = tid & 15;
                cp4(su32(&v_buf[nb][i][j]), gv + nt + (size_t)i * DK + vbase + j);
            }
        }
        cp_commit();

        // ---- process CSTEPS steps ----
        #pragma unroll
        for (int i = 0; i < CSTEPS; ++i) {
            const float4 k4 = *(const float4*)&k_buf[cur][i][lane << 2];
            const float4 q4 = *(const float4*)&q_buf[cur][i][lane << 2];
            const float  vv = v_buf[cur][i][wid];

            const ull k01 = pk(k4.x, k4.y), k23 = pk(k4.z, k4.w);
            const ull q01 = pk(q4.x, q4.y), q23 = pk(q4.z, q4.w);

            // U = c1*W - lr*beta*m   (pre-update)
            const ull U01 = fma2(C1, W01, mul2(NLRB, m01));
            const ull U23 = fma2(C1, W23, mul2(NLRB, m23));

            // three dots on pre-update state
            float swk = hadd2(fma2(W01, k01, mul2(W23, k23)));
            float suq = hadd2(fma2(U01, q01, mul2(U23, q23)));
            float skq = hadd2(fma2(k01, q01, mul2(k23, q23)));

            #pragma unroll
            for (int off = 16; off; off >>= 1) {
                swk += __shfl_xor_sync(0xffffffffu, swk, off);
                suq += __shfl_xor_sync(0xffffffffu, suq, off);
                skq += __shfl_xor_sync(0xffffffffu, skq, off);
            }

            const float r  = swk - vv;
            const float wr = -0.02f * r;        // -lr*2*(1-beta)*r
            if (lane == 0)
                y_buf[cur][i][wid] = fmaf(wr, skq, suq);

            const float gr = 0.2f * r;          // 2*(1-beta)*r
            const ull gr2 = pk(gr, gr);
            const ull wr2 = pk(wr, wr);

            m01 = fma2(gr2, k01, mul2(BETA2, m01));
            m23 = fma2(gr2, k23, mul2(BETA2, m23));
            W01 = fma2(wr2, k01, U01);
            W23 = fma2(wr2, k23, U23);
        }

        cp_wait_all();
        __syncthreads();

        // write back this chunk's outputs (y_buf[cur] is not reused until
        // chunk+2, which is gated by the barrier inside chunk+1)
        if (tid < CSTEPS * 16) {
            int i = tid >> 4, j = tid & 15;
            gy[(size_t)(t0 + i) * DK + vbase + j] = y_buf[cur][i][j];
        }
    }
}

extern "C" void kernel_launch(void* const* d_in, const int* in_sizes, int n_in,
                              void* d_out, int out_size) {
    const float* Q = (const float*)d_in[0];
    const float* K = (const float*)d_in[1];
    const float* V = (const float*)d_in[2];
    float* Y = (float*)d_out;
    (void)in_sizes; (void)n_in; (void)out_size;
    titans_kernel<<<128, 512>>>(Q, K, V, Y);
}